// round 9
// baseline (speedup 1.0000x reference)
#include <cuda_runtime.h>

#define NN   16384
#define EE   524288
#define DIN  256
#define DOUT 128
#define X_ELEMS (NN * DOUT)

#define NZCHUNKS  65536   // 65536 chunks x 1024 f4 x 16B = 1,073,741,824 B = all of A
#define CHUNK_F4  1024

// Scratch (no allocations allowed).
__device__ float    g_s[EE];     // per-edge exp(s)
__device__ float    g_ssum[NN];  // per-row sum of exp(s)
__device__ int      g_cnt[NN];   // per-row edge count (degenerate-row fallback)
__device__ float    g_sq[NN];    // per-row squared L2 norm of x
__device__ unsigned g_zctr;      // zero-chunk work queue (reset by scatter each launch)

// x = In[16384,256] @ W[256,128]. 128x128 tile, 8x8 reg tile (FFMA-bound).
// Triggers PDL completion at entry so score's zero phase overlaps.
__global__ __launch_bounds__(256) void gemm_kernel(const float* __restrict__ In,
                                                   const float* __restrict__ W,
                                                   float* __restrict__ X) {
#if __CUDA_ARCH__ >= 900
    cudaTriggerProgrammaticLaunchCompletion();
#endif
    __shared__ float Ast[32][132];   // A tile, k-major transposed, padded
    __shared__ float Bs[32][128];    // B tile
    __shared__ float ssq[128];

    const int tid  = threadIdx.x;
    const int brow = blockIdx.x * 128;
    const int tx   = tid & 15;
    const int ty   = tid >> 4;

    if (tid < 128) {
        g_ssum[brow + tid] = 0.0f;
        g_cnt[brow + tid]  = 0;
        ssq[tid] = 0.0f;
    }

    float acc[8][8];
#pragma unroll
    for (int i = 0; i < 8; i++)
#pragma unroll
        for (int j = 0; j < 8; j++) acc[i][j] = 0.0f;

    for (int k0 = 0; k0 < DIN; k0 += 32) {
#pragma unroll
        for (int i = 0; i < 4; i++) {
            int f  = tid + i * 256;
            int r  = f >> 3;
            int c4 = f & 7;
            float4 v = *(const float4*)(In + (size_t)(brow + r) * DIN + k0 + c4 * 4);
            Ast[c4 * 4 + 0][r] = v.x;
            Ast[c4 * 4 + 1][r] = v.y;
            Ast[c4 * 4 + 2][r] = v.z;
            Ast[c4 * 4 + 3][r] = v.w;
        }
#pragma unroll
        for (int i = 0; i < 4; i++) {
            int f = tid + i * 256;
            int r = f >> 5;
            int c = (f & 31) * 4;
            *(float4*)&Bs[r][c] = *(const float4*)(W + (size_t)(k0 + r) * DOUT + c);
        }
        __syncthreads();
#pragma unroll 4
        for (int k = 0; k < 32; k++) {
            float4 a0 = *(float4*)&Ast[k][ty * 8];
            float4 a1 = *(float4*)&Ast[k][ty * 8 + 4];
            float4 b0 = *(float4*)&Bs[k][tx * 8];
            float4 b1 = *(float4*)&Bs[k][tx * 8 + 4];
            float a[8] = {a0.x, a0.y, a0.z, a0.w, a1.x, a1.y, a1.z, a1.w};
            float b[8] = {b0.x, b0.y, b0.z, b0.w, b1.x, b1.y, b1.z, b1.w};
#pragma unroll
            for (int i = 0; i < 8; i++)
#pragma unroll
                for (int j = 0; j < 8; j++)
                    acc[i][j] = fmaf(a[i], b[j], acc[i][j]);
        }
        __syncthreads();
    }

#pragma unroll
    for (int i = 0; i < 8; i++) {
        int r = brow + ty * 8 + i;
        float4 o0 = {acc[i][0], acc[i][1], acc[i][2], acc[i][3]};
        float4 o1 = {acc[i][4], acc[i][5], acc[i][6], acc[i][7]};
        *(float4*)(X + (size_t)r * DOUT + tx * 8)     = o0;
        *(float4*)(X + (size_t)r * DOUT + tx * 8 + 4) = o1;
        float p = acc[i][0]*acc[i][0] + acc[i][1]*acc[i][1] + acc[i][2]*acc[i][2] + acc[i][3]*acc[i][3]
                + acc[i][4]*acc[i][4] + acc[i][5]*acc[i][5] + acc[i][6]*acc[i][6] + acc[i][7]*acc[i][7];
        atomicAdd(&ssq[ty * 8 + i], p);
    }
    __syncthreads();
    if (tid < 128) g_sq[brow + tid] = ssq[tid];
}

// Launched with ProgrammaticStreamSerialization: starts while gemm runs.
// Phase 1 (pre-sync, independent of X): dynamically claim 64KB zero chunks of A
// so resident blocks keep the HBM store pipe at its floor during all of gemm.
// Phase 2 (post cudaGridDependencySynchronize): per-edge score/exp/ssum.
__global__ __launch_bounds__(256) void score_kernel(const float* __restrict__ X,
                                                    const int* __restrict__ edge,
                                                    const float* __restrict__ a,
                                                    float* __restrict__ A) {
    const int tid = threadIdx.x;
    {
        __shared__ unsigned s_c;
        float4* A4 = reinterpret_cast<float4*>(A);
        const float4 z = make_float4(0.f, 0.f, 0.f, 0.f);
        for (;;) {
            if (tid == 0) s_c = atomicAdd(&g_zctr, 4);
            __syncthreads();
            unsigned c = s_c;
            __syncthreads();
            if (c >= NZCHUNKS) break;
            float4* dst = A4 + (size_t)c * CHUNK_F4;
#pragma unroll
            for (int i = 0; i < 16; i++)
                __stcs(dst + tid + i * 256, z);
        }
    }

#if __CUDA_ARCH__ >= 900
    cudaGridDependencySynchronize();   // wait for gemm (X, g_sq, ssum/cnt init)
#endif

    int e    = (int)(blockIdx.x * 8 + (tid >> 5));
    int lane = tid & 31;
    if (e >= EE) return;
    int row = edge[e];
    int col = edge[EE + e];

    float4 xi = *(const float4*)(X + (size_t)row * DOUT + lane * 4);
    float4 xj = *(const float4*)(X + (size_t)col * DOUT + lane * 4);
    float4 av = *(const float4*)(a + lane * 4);

    float t = fmaxf(xi.x * xj.x, 0.0f) * av.x
            + fmaxf(xi.y * xj.y, 0.0f) * av.y
            + fmaxf(xi.z * xj.z, 0.0f) * av.z
            + fmaxf(xi.w * xj.w, 0.0f) * av.w;
#pragma unroll
    for (int o = 16; o; o >>= 1) t += __shfl_down_sync(0xffffffffu, t, o);

    if (lane == 0) {
        // s bounded by ||a||_2 (~1.4) => exp cannot overflow; max-shift redundant.
        float ex = 0.0f;
        if (t > 0.0f) ex = __expf(t * rsqrtf(g_sq[row] * g_sq[col]));
        g_s[e] = ex;
        atomicAdd(&g_ssum[row], ex);
        atomicAdd(&g_cnt[row], 1);
    }
}

// vals = ex / ssum[row] (or 1/cnt for all-gated rows); scatter-add into A.
// Also resets the zero-chunk queue for the next graph replay.
__global__ void scatter_kernel(const int* __restrict__ edge, float* __restrict__ A) {
    if (blockIdx.x == 0 && threadIdx.x == 0) g_zctr = 0;
    int e = blockIdx.x * blockDim.x + threadIdx.x;
    if (e >= EE) return;
    int row = edge[e];
    int col = edge[EE + e];
    float denom = g_ssum[row];
    float v = (denom > 0.0f) ? (g_s[e] / denom) : (1.0f / (float)g_cnt[row]);
    atomicAdd(A + (size_t)row * NN + col, v);
}

extern "C" void kernel_launch(void* const* d_in, const int* in_sizes, int n_in,
                              void* d_out, int out_size) {
    const float* In   = (const float*)d_in[0];   // [16384, 256]
    const int*   edge = (const int*)d_in[1];     // [2, 524288]
    const float* W    = (const float*)d_in[2];   // [256, 128]
    const float* a    = (const float*)d_in[3];   // [128, 1]
    float* X = (float*)d_out;                    // [16384, 128]
    float* A = X + X_ELEMS;                      // [16384, 16384]

    gemm_kernel<<<NN / 128, 256>>>(In, W, X);

    // Score with programmatic dependent launch: overlaps its zero phase
    // with gemm, then grid-syncs before consuming X.
    {
        cudaLaunchConfig_t cfg = {};
        cfg.gridDim  = dim3(EE / 8);
        cfg.blockDim = dim3(256);
        cfg.stream   = 0;
        cudaLaunchAttribute attr[1];
        attr[0].id = cudaLaunchAttributeProgrammaticStreamSerialization;
        attr[0].val.programmaticStreamSerializationAllowed = 1;
        cfg.attrs = attr;
        cfg.numAttrs = 1;
        cudaLaunchKernelEx(&cfg, score_kernel, X, edge, a, A);
    }

    scatter_kernel<<<EE / 256, 256>>>(edge, A);
}